// round 2
// baseline (speedup 1.0000x reference)
#include <cuda_runtime.h>
#include <cuda_bf16.h>

// Problem constants: B=8, H=8, L=2048, D=64. BH = 64.
#define LSEQ 2048
#define DH   64
#define BM   16           // query rows per CTA
#define NT   (LSEQ / 64)  // 32 key/value tiles of 64 rows
#define THREADS 256

// smem: sS[16][2048] floats (131072 B) + sT[64][17] float4 (17408 B) + sInv[16] (64 B)
#define SMEM_BYTES (BM * LSEQ * 4 + 64 * 17 * 16 + 16 * 4)

__global__ __launch_bounds__(THREADS, 1)
void sdpa_fused_kernel(const float* __restrict__ Q,
                       const float* __restrict__ K,
                       const float* __restrict__ V,
                       float* __restrict__ res,
                       float* __restrict__ att) {
    extern __shared__ float smem[];
    float*  sS   = smem;                              // [BM][LSEQ]
    float4* sT   = (float4*)(smem + BM * LSEQ);       // [64][17] padded tile
    float*  sInv = (float*)(sT + 64 * 17);            // [BM]

    const int bh  = blockIdx.y;        // 0..63
    const int qt  = blockIdx.x;        // 0..127
    const int tid = threadIdx.x;
    const int r   = tid >> 4;          // 0..15  (query row within tile)
    const int cs  = tid & 15;          // 0..15  (column lane)

    const float4* Qg = (const float4*)(Q + ((size_t)bh * LSEQ + (size_t)qt * BM) * DH);
    const float4* Kg = (const float4*)(K + (size_t)bh * LSEQ * DH);
    const float4* Vg = (const float4*)(V + (size_t)bh * LSEQ * DH);

    // ---- cache this thread's query row in registers, pre-scaled by 1/head_sz ----
    const float inv_d = 1.0f / 64.0f;   // reference divides by head_sz (NOT sqrt)
    float4 qreg[16];
    #pragma unroll
    for (int i = 0; i < 16; i++) {
        float4 t = Qg[r * 16 + i];
        qreg[i] = make_float4(t.x * inv_d, t.y * inv_d, t.z * inv_d, t.w * inv_d);
    }

    // ================= QK^T : fill sS[16][2048] =================
    for (int nt = 0; nt < NT; nt++) {
        // stage K tile (rows nt*64 .. +63), coalesced float4 loads
        #pragma unroll
        for (int i = 0; i < 4; i++) {
            int idx = tid + i * THREADS;          // 0..1023
            int row = idx >> 4, col = idx & 15;
            sT[row * 17 + col] = Kg[(nt * 64 + row) * 16 + col];
        }
        __syncthreads();

        #pragma unroll
        for (int cc = 0; cc < 4; cc++) {
            int c = cs + cc * 16;
            float acc = 0.f;
            #pragma unroll
            for (int d4 = 0; d4 < 16; d4++) {
                float4 k = sT[c * 17 + d4];
                acc = fmaf(qreg[d4].x, k.x, acc);
                acc = fmaf(qreg[d4].y, k.y, acc);
                acc = fmaf(qreg[d4].z, k.z, acc);
                acc = fmaf(qreg[d4].w, k.w, acc);
            }
            sS[r * LSEQ + nt * 64 + c] = acc;
        }
        __syncthreads();
    }

    // ================= softmax over each row (16 lanes per row) =================
    float m = -1e30f;
    for (int j = cs; j < LSEQ; j += 16) m = fmaxf(m, sS[r * LSEQ + j]);
    #pragma unroll
    for (int o = 8; o; o >>= 1) m = fmaxf(m, __shfl_xor_sync(0xffffffffu, m, o));

    float s = 0.f;
    for (int j = cs; j < LSEQ; j += 16) {
        float e = __expf(sS[r * LSEQ + j] - m);
        sS[r * LSEQ + j] = e;
        s += e;
    }
    #pragma unroll
    for (int o = 8; o; o >>= 1) s += __shfl_xor_sync(0xffffffffu, s, o);
    if (cs == 0) sInv[r] = 1.0f / s;
    __syncthreads();

    // ---- normalize in smem + coalesced float4 store of att ----
    float4* att4 = (float4*)(att + ((size_t)bh * LSEQ + (size_t)qt * BM) * LSEQ);
    float4* sS4  = (float4*)sS;
    #pragma unroll
    for (int i = 0; i < (BM * LSEQ / 4) / THREADS; i++) {   // 32 iters
        int idx = tid + i * THREADS;                         // 0..8191 float4s
        int row = idx >> 9;                                  // / (LSEQ/4)
        float inv = sInv[row];
        float4 v = sS4[idx];
        v.x *= inv; v.y *= inv; v.z *= inv; v.w *= inv;
        sS4[idx] = v;
        att4[idx] = v;
    }
    __syncthreads();

    // ================= att @ V : res[16][64] =================
    float4 acc = make_float4(0.f, 0.f, 0.f, 0.f);
    for (int nt = 0; nt < NT; nt++) {
        #pragma unroll
        for (int i = 0; i < 4; i++) {
            int idx = tid + i * THREADS;
            int row = idx >> 4, col = idx & 15;
            sT[row * 17 + col] = Vg[(nt * 64 + row) * 16 + col];
        }
        __syncthreads();

        #pragma unroll
        for (int mm = 0; mm < 64; mm++) {
            float a = sS[r * LSEQ + nt * 64 + mm];   // broadcast across 16 lanes
            float4 v = sT[mm * 17 + cs];
            acc.x = fmaf(a, v.x, acc.x);
            acc.y = fmaf(a, v.y, acc.y);
            acc.z = fmaf(a, v.z, acc.z);
            acc.w = fmaf(a, v.w, acc.w);
        }
        __syncthreads();
    }

    float4* res4 = (float4*)(res + ((size_t)bh * LSEQ + (size_t)qt * BM + r) * DH);
    res4[cs] = acc;
}

extern "C" void kernel_launch(void* const* d_in, const int* in_sizes, int n_in,
                              void* d_out, int out_size) {
    const float* Q = (const float*)d_in[0];
    const float* K = (const float*)d_in[1];
    const float* V = (const float*)d_in[2];

    float* out = (float*)d_out;
    // Output tuple (res, att) flattened: res = 8*8*2048*64 = 8388608 floats first,
    // then att = 8*8*2048*2048 floats.
    float* res = out;
    float* att = out + (size_t)8 * 8 * 2048 * 64;

    cudaFuncSetAttribute(sdpa_fused_kernel,
                         cudaFuncAttributeMaxDynamicSharedMemorySize, SMEM_BYTES);

    dim3 grid(LSEQ / BM, 64);   // 128 query tiles x 64 (b,h) pairs
    sdpa_fused_kernel<<<grid, THREADS, SMEM_BYTES>>>(Q, K, V, res, att);
}

// round 4
// speedup vs baseline: 2.2194x; 2.2194x over previous
#include <cuda_runtime.h>
#include <cuda_bf16.h>

// B=8, H=8, L=2048, D=64
#define LSEQ 2048
#define DH   64
#define BM   16
#define NT   32          // 32 key tiles of 64
#define THREADS 256
#define SW   2052        // sS row stride in floats (2052 mod 32 == 4)
#define KSTR 68          // K tile row stride (68 mod 32 == 4)
#define VSTR 72          // V/Q tile row stride (72 mod 32 == 8)
#define TILE_FLOATS (64 * VSTR)
#define SMEM_BYTES ((BM * SW + TILE_FLOATS + 16) * 4)

__device__ __forceinline__ unsigned f2tf(float f) {
    unsigned u;
    asm("cvt.rna.tf32.f32 %0, %1;" : "=r"(u) : "f"(f));
    return u;
}

__device__ __forceinline__ void mma8(float* c, const unsigned* a, unsigned b0, unsigned b1) {
    asm volatile(
        "mma.sync.aligned.m16n8k8.row.col.f32.tf32.tf32.f32 "
        "{%0,%1,%2,%3}, {%4,%5,%6,%7}, {%8,%9}, {%0,%1,%2,%3};"
        : "+f"(c[0]), "+f"(c[1]), "+f"(c[2]), "+f"(c[3])
        : "r"(a[0]), "r"(a[1]), "r"(a[2]), "r"(a[3]), "r"(b0), "r"(b1));
}

__global__ __launch_bounds__(THREADS, 1)
void sdpa_tf32_kernel(const float* __restrict__ Q,
                      const float* __restrict__ K,
                      const float* __restrict__ V,
                      float* __restrict__ res,
                      float* __restrict__ att) {
    extern __shared__ float smem[];
    float*  sS   = smem;                          // [16][SW]
    float*  sT   = smem + BM * SW;                // staging tile (K/V/Q)
    float*  sInv = sT + TILE_FLOATS;              // [16]
    float4* sT4  = (float4*)sT;
    float4* sS4  = (float4*)sS;

    const int bh   = blockIdx.y;
    const int qt   = blockIdx.x;
    const int tid  = threadIdx.x;
    const int warp = tid >> 5;
    const int lane = tid & 31;
    const int g    = lane >> 2;   // 0..7
    const int tg   = lane & 3;    // 0..3

    const float4* Qg = (const float4*)(Q + ((size_t)bh * LSEQ + (size_t)qt * BM) * DH);
    const float4* Kg = (const float4*)(K + (size_t)bh * LSEQ * DH);
    const float4* Vg = (const float4*)(V + (size_t)bh * LSEQ * DH);

    // ---------------- stage Q (scaled by 1/64) and build A fragments ----------------
    {
        const float inv_d = 1.0f / 64.0f;
        int row = tid >> 4, col = tid & 15;
        float4 t = Qg[row * 16 + col];
        t.x *= inv_d; t.y *= inv_d; t.z *= inv_d; t.w *= inv_d;
        sT4[row * (VSTR / 4) + col] = t;
    }
    __syncthreads();

    unsigned qa[8][4];
    #pragma unroll
    for (int ks = 0; ks < 8; ks++) {
        qa[ks][0] = f2tf(sT[g * VSTR + ks * 8 + tg]);
        qa[ks][1] = f2tf(sT[(g + 8) * VSTR + ks * 8 + tg]);
        qa[ks][2] = f2tf(sT[g * VSTR + ks * 8 + tg + 4]);
        qa[ks][3] = f2tf(sT[(g + 8) * VSTR + ks * 8 + tg + 4]);
    }
    __syncthreads();

    // ---------------- QK^T : S[16][2048] via tf32 mma ----------------
    const int n0 = warp * 8;
    for (int nt = 0; nt < NT; nt++) {
        #pragma unroll
        for (int i = 0; i < 4; i++) {
            int idx = tid + i * THREADS;
            int row = idx >> 4, col = idx & 15;
            sT4[row * (KSTR / 4) + col] = Kg[(nt * 64 + row) * 16 + col];
        }
        __syncthreads();

        float cA[4] = {0.f, 0.f, 0.f, 0.f};
        float cB[4] = {0.f, 0.f, 0.f, 0.f};
        #pragma unroll
        for (int ks = 0; ks < 4; ks++) {
            unsigned b0 = f2tf(sT[(n0 + g) * KSTR + ks * 8 + tg]);
            unsigned b1 = f2tf(sT[(n0 + g) * KSTR + ks * 8 + tg + 4]);
            mma8(cA, qa[ks], b0, b1);
            unsigned d0 = f2tf(sT[(n0 + g) * KSTR + (ks + 4) * 8 + tg]);
            unsigned d1 = f2tf(sT[(n0 + g) * KSTR + (ks + 4) * 8 + tg + 4]);
            mma8(cB, qa[ks + 4], d0, d1);
        }
        int col = nt * 64 + n0 + 2 * tg;
        *(float2*)&sS[g * SW + col]       = make_float2(cA[0] + cB[0], cA[1] + cB[1]);
        *(float2*)&sS[(g + 8) * SW + col] = make_float2(cA[2] + cB[2], cA[3] + cB[3]);
        __syncthreads();
    }

    // ---------------- softmax per row (16 lanes per row) ----------------
    {
        const int r = tid >> 4, cs = tid & 15;
        float m = -1e30f;
        for (int j = cs; j < LSEQ; j += 16) m = fmaxf(m, sS[r * SW + j]);
        #pragma unroll
        for (int o = 8; o; o >>= 1) m = fmaxf(m, __shfl_xor_sync(0xffffffffu, m, o));

        float s = 0.f;
        for (int j = cs; j < LSEQ; j += 16) {
            float e = __expf(sS[r * SW + j] - m);
            sS[r * SW + j] = e;
            s += e;
        }
        #pragma unroll
        for (int o = 8; o; o >>= 1) s += __shfl_xor_sync(0xffffffffu, s, o);
        if (cs == 0) sInv[r] = 1.0f / s;
    }
    __syncthreads();

    // ---------------- normalize: store att (fp32) + keep tf32-rounded P in smem ----------------
    float4* att4 = (float4*)(att + ((size_t)bh * LSEQ + (size_t)qt * BM) * LSEQ);
    #pragma unroll
    for (int i = 0; i < 32; i++) {
        int idx = tid + i * THREADS;          // 0..8191
        int row = idx >> 9, c4 = idx & 511;
        float inv = sInv[row];
        float4 v = sS4[row * (SW / 4) + c4];
        v.x *= inv; v.y *= inv; v.z *= inv; v.w *= inv;
        att4[row * 512 + c4] = v;
        v.x = __uint_as_float(f2tf(v.x));
        v.y = __uint_as_float(f2tf(v.y));
        v.z = __uint_as_float(f2tf(v.z));
        v.w = __uint_as_float(f2tf(v.w));
        sS4[row * (SW / 4) + c4] = v;
    }
    __syncthreads();

    // ---------------- att @ V : res[16][64] via tf32 mma ----------------
    float oA[4] = {0.f, 0.f, 0.f, 0.f};
    float oB[4] = {0.f, 0.f, 0.f, 0.f};
    for (int nt = 0; nt < NT; nt++) {
        #pragma unroll
        for (int i = 0; i < 4; i++) {
            int idx = tid + i * THREADS;
            int row = idx >> 4, col = idx & 15;
            sT4[row * (VSTR / 4) + col] = Vg[(nt * 64 + row) * 16 + col];
        }
        __syncthreads();

        #pragma unroll
        for (int ks = 0; ks < 8; ks += 2) {
            unsigned a[4];
            int k0 = nt * 64 + ks * 8;
            a[0] = __float_as_uint(sS[g * SW + k0 + tg]);
            a[1] = __float_as_uint(sS[(g + 8) * SW + k0 + tg]);
            a[2] = __float_as_uint(sS[g * SW + k0 + tg + 4]);
            a[3] = __float_as_uint(sS[(g + 8) * SW + k0 + tg + 4]);
            unsigned b0 = f2tf(sT[(ks * 8 + tg) * VSTR + n0 + g]);
            unsigned b1 = f2tf(sT[(ks * 8 + tg + 4) * VSTR + n0 + g]);
            mma8(oA, a, b0, b1);

            k0 += 8;
            a[0] = __float_as_uint(sS[g * SW + k0 + tg]);
            a[1] = __float_as_uint(sS[(g + 8) * SW + k0 + tg]);
            a[2] = __float_as_uint(sS[g * SW + k0 + tg + 4]);
            a[3] = __float_as_uint(sS[(g + 8) * SW + k0 + tg + 4]);
            unsigned c0 = f2tf(sT[((ks + 1) * 8 + tg) * VSTR + n0 + g]);
            unsigned c1 = f2tf(sT[((ks + 1) * 8 + tg + 4) * VSTR + n0 + g]);
            mma8(oB, a, c0, c1);
        }
        __syncthreads();
    }

    // store res: warp covers d-cols [warp*8, warp*8+8), rows g and g+8
    {
        size_t base = ((size_t)bh * LSEQ + (size_t)qt * BM) * DH;
        int col = n0 + 2 * tg;
        *(float2*)&res[base + (size_t)g * DH + col] =
            make_float2(oA[0] + oB[0], oA[1] + oB[1]);
        *(float2*)&res[base + (size_t)(g + 8) * DH + col] =
            make_float2(oA[2] + oB[2], oA[3] + oB[3]);
    }
}

extern "C" void kernel_launch(void* const* d_in, const int* in_sizes, int n_in,
                              void* d_out, int out_size) {
    const float* Q = (const float*)d_in[0];
    const float* K = (const float*)d_in[1];
    const float* V = (const float*)d_in[2];

    float* out = (float*)d_out;
    float* res = out;
    float* att = out + (size_t)8 * 8 * 2048 * 64;

    cudaFuncSetAttribute(sdpa_tf32_kernel,
                         cudaFuncAttributeMaxDynamicSharedMemorySize, SMEM_BYTES);

    dim3 grid(LSEQ / BM, 64);
    sdpa_tf32_kernel<<<grid, THREADS, SMEM_BYTES>>>(Q, K, V, res, att);
}

// round 5
// speedup vs baseline: 5.7267x; 2.5803x over previous
#include <cuda_runtime.h>
#include <cuda_bf16.h>

// B=8, H=8, L=2048, D=64, BH=64
#define LSEQ 2048
#define DH   64

// ---------- helpers ----------
__device__ __forceinline__ unsigned f2tf(float f) {
    unsigned u;
    asm("cvt.rna.tf32.f32 %0, %1;" : "=r"(u) : "f"(f));
    return u;
}

__device__ __forceinline__ void mma8(float* c, const unsigned* a, unsigned b0, unsigned b1) {
    asm volatile(
        "mma.sync.aligned.m16n8k8.row.col.f32.tf32.tf32.f32 "
        "{%0,%1,%2,%3}, {%4,%5,%6,%7}, {%8,%9}, {%0,%1,%2,%3};"
        : "+f"(c[0]), "+f"(c[1]), "+f"(c[2]), "+f"(c[3])
        : "r"(a[0]), "r"(a[1]), "r"(a[2]), "r"(a[3]), "r"(b0), "r"(b1));
}

// exp(x) for x <= 0 via FMA-pipe polynomial (no MUFU). ~2.4e-6 rel err.
__device__ __forceinline__ float fexp(float x) {
    x = fmaxf(x, -80.0f);
    const float L2E = 1.4426950408889634f;
    float t = fmaf(x, L2E, 12582912.0f);      // round(x*log2e) via 1.5*2^23 trick
    float n = t - 12582912.0f;
    float f = fmaf(x, L2E, -n);               // f in [-0.5, 0.5]
    float p = 1.33335581e-3f;
    p = fmaf(p, f, 9.61812910e-3f);
    p = fmaf(p, f, 5.55041086e-2f);
    p = fmaf(p, f, 2.40226507e-1f);
    p = fmaf(p, f, 6.93147181e-1f);
    p = fmaf(p, f, 1.0f);
    unsigned bits = (unsigned)(((int)n + 127) << 23);
    return p * __uint_as_float(bits);
}

// =====================================================================
// Kernel A: S = (Q K^T)/64  -> att buffer (raw logits)
// CTA: 128x128 tile, K=64. 256 threads, warp tile 64x32.
// =====================================================================
#define ASTR 68   // smem row stride (floats); 68 mod 32 == 4

__global__ __launch_bounds__(256)
void qk_kernel(const float* __restrict__ Q, const float* __restrict__ K,
               float* __restrict__ att) {
    extern __shared__ float sm[];
    float* sQ = sm;                 // [128][ASTR]
    float* sK = sm + 128 * ASTR;    // [128][ASTR]
    float4* sQ4 = (float4*)sQ;
    float4* sK4 = (float4*)sK;

    const int nt = blockIdx.x, mt = blockIdx.y, bh = blockIdx.z;
    const int tid = threadIdx.x;
    const int warp = tid >> 5, lane = tid & 31;
    const int g = lane >> 2, tg = lane & 3;
    const int wm = warp >> 2;   // 0..1 -> 64-row half
    const int wn = warp & 3;    // 0..3 -> 32-col quarter

    const float4* Qg = (const float4*)(Q + ((size_t)bh * LSEQ + (size_t)mt * 128) * DH);
    const float4* Kg = (const float4*)(K + ((size_t)bh * LSEQ + (size_t)nt * 128) * DH);

    const float inv_d = 1.0f / 64.0f;
    #pragma unroll
    for (int i = 0; i < 8; i++) {
        int idx = tid + i * 256;          // 0..2047
        int row = idx >> 4, c4 = idx & 15;
        float4 q = Qg[row * 16 + c4];
        q.x = __uint_as_float(f2tf(q.x * inv_d));
        q.y = __uint_as_float(f2tf(q.y * inv_d));
        q.z = __uint_as_float(f2tf(q.z * inv_d));
        q.w = __uint_as_float(f2tf(q.w * inv_d));
        sQ4[row * (ASTR / 4) + c4] = q;
        float4 k = Kg[row * 16 + c4];
        k.x = __uint_as_float(f2tf(k.x));
        k.y = __uint_as_float(f2tf(k.y));
        k.z = __uint_as_float(f2tf(k.z));
        k.w = __uint_as_float(f2tf(k.w));
        sK4[row * (ASTR / 4) + c4] = k;
    }
    __syncthreads();

    float acc[4][4][4];
    #pragma unroll
    for (int mi = 0; mi < 4; mi++)
        #pragma unroll
        for (int ni = 0; ni < 4; ni++)
            #pragma unroll
            for (int j = 0; j < 4; j++) acc[mi][ni][j] = 0.f;

    #pragma unroll
    for (int ks = 0; ks < 8; ks++) {
        unsigned a[4][4], b[4][2];
        #pragma unroll
        for (int mi = 0; mi < 4; mi++) {
            int row = wm * 64 + mi * 16;
            a[mi][0] = __float_as_uint(sQ[(row + g) * ASTR + ks * 8 + tg]);
            a[mi][1] = __float_as_uint(sQ[(row + 8 + g) * ASTR + ks * 8 + tg]);
            a[mi][2] = __float_as_uint(sQ[(row + g) * ASTR + ks * 8 + tg + 4]);
            a[mi][3] = __float_as_uint(sQ[(row + 8 + g) * ASTR + ks * 8 + tg + 4]);
        }
        #pragma unroll
        for (int ni = 0; ni < 4; ni++) {
            int col = wn * 32 + ni * 8;
            b[ni][0] = __float_as_uint(sK[(col + g) * ASTR + ks * 8 + tg]);
            b[ni][1] = __float_as_uint(sK[(col + g) * ASTR + ks * 8 + tg + 4]);
        }
        #pragma unroll
        for (int mi = 0; mi < 4; mi++)
            #pragma unroll
            for (int ni = 0; ni < 4; ni++)
                mma8(acc[mi][ni], a[mi], b[ni][0], b[ni][1]);
    }

    float* attR = att + (size_t)bh * LSEQ * LSEQ;
    #pragma unroll
    for (int mi = 0; mi < 4; mi++) {
        #pragma unroll
        for (int ni = 0; ni < 4; ni++) {
            int row = mt * 128 + wm * 64 + mi * 16 + g;
            int col = nt * 128 + wn * 32 + ni * 8 + 2 * tg;
            *(float2*)&attR[(size_t)row * LSEQ + col] =
                make_float2(acc[mi][ni][0], acc[mi][ni][1]);
            *(float2*)&attR[(size_t)(row + 8) * LSEQ + col] =
                make_float2(acc[mi][ni][2], acc[mi][ni][3]);
        }
    }
}

// =====================================================================
// Kernel B: row-wise softmax in place on att. One warp per row,
// row fully register-resident (64 floats/lane), poly exp.
// =====================================================================
__global__ __launch_bounds__(256)
void softmax_kernel(float* __restrict__ att) {
    const int warp = threadIdx.x >> 5, lane = threadIdx.x & 31;
    const size_t row = (size_t)blockIdx.x * 8 + warp;   // 0..131071
    float4* p = (float4*)(att + row * LSEQ);

    float4 v[16];
    float m = -1e30f;
    #pragma unroll
    for (int i = 0; i < 16; i++) {
        v[i] = p[lane + i * 32];
        m = fmaxf(m, fmaxf(fmaxf(v[i].x, v[i].y), fmaxf(v[i].z, v[i].w)));
    }
    #pragma unroll
    for (int o = 16; o; o >>= 1) m = fmaxf(m, __shfl_xor_sync(0xffffffffu, m, o));

    float s = 0.f;
    #pragma unroll
    for (int i = 0; i < 16; i++) {
        v[i].x = fexp(v[i].x - m);
        v[i].y = fexp(v[i].y - m);
        v[i].z = fexp(v[i].z - m);
        v[i].w = fexp(v[i].w - m);
        s += (v[i].x + v[i].y) + (v[i].z + v[i].w);
    }
    #pragma unroll
    for (int o = 16; o; o >>= 1) s += __shfl_xor_sync(0xffffffffu, s, o);
    float inv = 1.0f / s;

    #pragma unroll
    for (int i = 0; i < 16; i++) {
        v[i].x *= inv; v[i].y *= inv; v[i].z *= inv; v[i].w *= inv;
        p[lane + i * 32] = v[i];
    }
}

// =====================================================================
// Kernel C: res = att @ V. CTA: 64 rows x 64 cols, K-loop over 2048.
// 256 threads, warp tile 16x32 (4 wm x 2 wn).
// =====================================================================
#define PSTR 68   // att tile stride (mod 32 == 4)
#define VSTR 72   // V tile stride  (mod 32 == 8)

__global__ __launch_bounds__(256)
void av_kernel(const float* __restrict__ att, const float* __restrict__ V,
               float* __restrict__ res) {
    __shared__ float sP[64 * PSTR];
    __shared__ float sV[64 * VSTR];
    float4* sP4 = (float4*)sP;
    float4* sV4 = (float4*)sV;

    const int mt = blockIdx.x, bh = blockIdx.y;
    const int tid = threadIdx.x;
    const int warp = tid >> 5, lane = tid & 31;
    const int g = lane >> 2, tg = lane & 3;
    const int wm = warp >> 1;   // 0..3 -> 16-row slice
    const int wn = warp & 1;    // 0..1 -> 32-col half

    const float4* Pg = (const float4*)(att + ((size_t)bh * LSEQ + (size_t)mt * 64) * LSEQ);
    const float4* Vg = (const float4*)(V + (size_t)bh * LSEQ * DH);

    float acc[4][4];
    #pragma unroll
    for (int ni = 0; ni < 4; ni++)
        #pragma unroll
        for (int j = 0; j < 4; j++) acc[ni][j] = 0.f;

    for (int kt = 0; kt < 32; kt++) {
        #pragma unroll
        for (int i = 0; i < 4; i++) {
            int idx = tid + i * 256;       // 0..1023
            int row = idx >> 4, c4 = idx & 15;
            float4 a = Pg[(size_t)row * 512 + kt * 16 + c4];
            a.x = __uint_as_float(f2tf(a.x));
            a.y = __uint_as_float(f2tf(a.y));
            a.z = __uint_as_float(f2tf(a.z));
            a.w = __uint_as_float(f2tf(a.w));
            sP4[row * (PSTR / 4) + c4] = a;
            float4 b = Vg[(kt * 64 + row) * 16 + c4];
            b.x = __uint_as_float(f2tf(b.x));
            b.y = __uint_as_float(f2tf(b.y));
            b.z = __uint_as_float(f2tf(b.z));
            b.w = __uint_as_float(f2tf(b.w));
            sV4[row * (VSTR / 4) + c4] = b;
        }
        __syncthreads();

        #pragma unroll
        for (int ks = 0; ks < 8; ks++) {
            unsigned a[4], b[4][2];
            int row0 = wm * 16;
            a[0] = __float_as_uint(sP[(row0 + g) * PSTR + ks * 8 + tg]);
            a[1] = __float_as_uint(sP[(row0 + 8 + g) * PSTR + ks * 8 + tg]);
            a[2] = __float_as_uint(sP[(row0 + g) * PSTR + ks * 8 + tg + 4]);
            a[3] = __float_as_uint(sP[(row0 + 8 + g) * PSTR + ks * 8 + tg + 4]);
            #pragma unroll
            for (int ni = 0; ni < 4; ni++) {
                int col = wn * 32 + ni * 8;
                b[ni][0] = __float_as_uint(sV[(ks * 8 + tg) * VSTR + col + g]);
                b[ni][1] = __float_as_uint(sV[(ks * 8 + tg + 4) * VSTR + col + g]);
            }
            #pragma unroll
            for (int ni = 0; ni < 4; ni++)
                mma8(acc[ni], a, b[ni][0], b[ni][1]);
        }
        __syncthreads();
    }

    float* resR = res + ((size_t)bh * LSEQ + (size_t)mt * 64) * DH;
    #pragma unroll
    for (int ni = 0; ni < 4; ni++) {
        int row = wm * 16 + g;
        int col = wn * 32 + ni * 8 + 2 * tg;
        *(float2*)&resR[(size_t)row * DH + col] = make_float2(acc[ni][0], acc[ni][1]);
        *(float2*)&resR[(size_t)(row + 8) * DH + col] = make_float2(acc[ni][2], acc[ni][3]);
    }
}

// =====================================================================
extern "C" void kernel_launch(void* const* d_in, const int* in_sizes, int n_in,
                              void* d_out, int out_size) {
    const float* Q = (const float*)d_in[0];
    const float* K = (const float*)d_in[1];
    const float* V = (const float*)d_in[2];

    float* out = (float*)d_out;
    float* res = out;
    float* att = out + (size_t)8 * 8 * 2048 * 64;

    static int inited = 0;
    if (!inited) {
        cudaFuncSetAttribute(qk_kernel,
            cudaFuncAttributeMaxDynamicSharedMemorySize, 2 * 128 * ASTR * 4);
        inited = 1;
    }

    dim3 gA(16, 16, 64);
    qk_kernel<<<gA, 256, 2 * 128 * ASTR * 4>>>(Q, K, att);

    softmax_kernel<<<131072 / 8, 256>>>(att);

    dim3 gC(32, 64);
    av_kernel<<<gC, 256>>>(att, V, res);
}